// round 3
// baseline (speedup 1.0000x reference)
#include <cuda_runtime.h>
#include <cstdint>

// Problem constants
#define BB   4096
#define NN   512
#define MM   64
#define SEQW 8
#define HID  256
#define COUT 128
#define INSZ 73          // SEQW+1 + MM
#define PSZ  70          // M + 1 + 1 + 3 + 1
#define RSZ  268         // 2*PSZ + 2*M

// scratch (device globals: no allocation allowed)
__device__ float g_repr[BB * RSZ];
__device__ float g_ctrl[BB * COUT];

__device__ __forceinline__ float softplusf(float x) {
    return fmaxf(x, 0.f) + log1pf(expf(-fabsf(x)));
}
__device__ __forceinline__ float sigmf(float x) {
    return 1.f / (1.f + __expf(-x));
}
__device__ __forceinline__ float leakyf(float x) {
    return x > 0.f ? x : 0.01f * x;
}

// ---------------------------------------------------------------------------
// Kernel 1: controller MLP. 32 batch rows per CTA, 256 threads.
// Activations stored transposed in smem with stride 36 (9j+k mod 32 -> no bank
// conflicts on float4 stores).
// ---------------------------------------------------------------------------
#define TB 32
#define AST 36
#define SMEM1_BYTES (2 * 256 * AST * 4)

__global__ void __launch_bounds__(256, 1) ctrl_kernel(
    const float* __restrict__ x, const float* __restrict__ prev_read,
    const float* __restrict__ W0, const float* __restrict__ b0,
    const float* __restrict__ W1, const float* __restrict__ b1,
    const float* __restrict__ Wout, const float* __restrict__ bout,
    const float* __restrict__ reprW, const float* __restrict__ reprb)
{
    extern __shared__ float sm1[];
    float* A  = sm1;                // 256*36
    float* Bf = sm1 + 256 * AST;    // 256*36
    const int tid = threadIdx.x;
    const int r0  = blockIdx.x * TB;

    // load ctrl_in transposed: A[i*36 + r]
    for (int idx = tid; idx < INSZ * TB; idx += 256) {
        int i = idx >> 5, r = idx & 31;
        float v = (i < SEQW + 1) ? x[(size_t)(r0 + r) * (SEQW + 1) + i]
                                 : prev_read[(size_t)(r0 + r) * MM + (i - SEQW - 1)];
        A[i * AST + r] = v;
    }
    __syncthreads();

    // layer 1: INSZ -> 256, A -> Bf
    {
        const int j = tid;
        float4 acc[8];
        #pragma unroll
        for (int q = 0; q < 8; ++q) acc[q] = make_float4(0.f, 0.f, 0.f, 0.f);
        for (int i = 0; i < INSZ; ++i) {
            float w = W0[i * 256 + j];
            const float4* src = (const float4*)&A[i * AST];
            #pragma unroll
            for (int q = 0; q < 8; ++q) {
                float4 v = src[q];
                acc[q].x += w * v.x; acc[q].y += w * v.y;
                acc[q].z += w * v.z; acc[q].w += w * v.w;
            }
        }
        float bb = b0[j];
        float4* dst = (float4*)&Bf[j * AST];
        #pragma unroll
        for (int q = 0; q < 8; ++q) {
            float4 v = acc[q];
            v.x = leakyf(v.x + bb); v.y = leakyf(v.y + bb);
            v.z = leakyf(v.z + bb); v.w = leakyf(v.w + bb);
            dst[q] = v;
        }
    }
    __syncthreads();

    // layer 2: 256 -> 256, Bf -> A
    {
        const int j = tid;
        float4 acc[8];
        #pragma unroll
        for (int q = 0; q < 8; ++q) acc[q] = make_float4(0.f, 0.f, 0.f, 0.f);
        for (int i = 0; i < HID; ++i) {
            float w = W1[i * 256 + j];
            const float4* src = (const float4*)&Bf[i * AST];
            #pragma unroll
            for (int q = 0; q < 8; ++q) {
                float4 v = src[q];
                acc[q].x += w * v.x; acc[q].y += w * v.y;
                acc[q].z += w * v.z; acc[q].w += w * v.w;
            }
        }
        float bb = b1[j];
        float4* dst = (float4*)&A[j * AST];
        #pragma unroll
        for (int q = 0; q < 8; ++q) {
            float4 v = acc[q];
            v.x = leakyf(v.x + bb); v.y = leakyf(v.y + bb);
            v.z = leakyf(v.z + bb); v.w = leakyf(v.w + bb);
            dst[q] = v;
        }
    }
    __syncthreads();

    // layer 3: 256 -> 128, A -> Bf (tanh), also write g_ctrl
    if (tid < COUT) {
        const int j = tid;
        float4 acc[8];
        #pragma unroll
        for (int q = 0; q < 8; ++q) acc[q] = make_float4(0.f, 0.f, 0.f, 0.f);
        for (int i = 0; i < HID; ++i) {
            float w = Wout[i * COUT + j];
            const float4* src = (const float4*)&A[i * AST];
            #pragma unroll
            for (int q = 0; q < 8; ++q) {
                float4 v = src[q];
                acc[q].x += w * v.x; acc[q].y += w * v.y;
                acc[q].z += w * v.z; acc[q].w += w * v.w;
            }
        }
        float bb = bout[j];
        #pragma unroll
        for (int q = 0; q < 8; ++q) {
            float4 v = acc[q];
            v.x = tanhf(v.x + bb); v.y = tanhf(v.y + bb);
            v.z = tanhf(v.z + bb); v.w = tanhf(v.w + bb);
            ((float4*)&Bf[j * AST])[q] = v;
            g_ctrl[(size_t)(r0 + q * 4 + 0) * COUT + j] = v.x;
            g_ctrl[(size_t)(r0 + q * 4 + 1) * COUT + j] = v.y;
            g_ctrl[(size_t)(r0 + q * 4 + 2) * COUT + j] = v.z;
            g_ctrl[(size_t)(r0 + q * 4 + 3) * COUT + j] = v.w;
        }
    }
    __syncthreads();

    // layer 4: 128 -> 268 (repr), Bf -> g_repr
    for (int o = tid; o < RSZ; o += 256) {
        float4 acc[8];
        #pragma unroll
        for (int q = 0; q < 8; ++q) acc[q] = make_float4(0.f, 0.f, 0.f, 0.f);
        for (int i = 0; i < COUT; ++i) {
            float w = reprW[i * RSZ + o];
            const float4* src = (const float4*)&Bf[i * AST];
            #pragma unroll
            for (int q = 0; q < 8; ++q) {
                float4 v = src[q];
                acc[q].x += w * v.x; acc[q].y += w * v.y;
                acc[q].z += w * v.z; acc[q].w += w * v.w;
            }
        }
        float bb = reprb[o];
        #pragma unroll
        for (int q = 0; q < 8; ++q) {
            g_repr[(size_t)(r0 + q * 4 + 0) * RSZ + o] = acc[q].x + bb;
            g_repr[(size_t)(r0 + q * 4 + 1) * RSZ + o] = acc[q].y + bb;
            g_repr[(size_t)(r0 + q * 4 + 2) * RSZ + o] = acc[q].z + bb;
            g_repr[(size_t)(r0 + q * 4 + 3) * RSZ + o] = acc[q].w + bb;
        }
    }
}

// ---------------------------------------------------------------------------
// Kernel 2: per-batch-row addressing + memory read + bank update + seq_out.
// One CTA per b, 512 threads, full bank[b] (128 KB) staged in smem via cp.async.
// ---------------------------------------------------------------------------
#define SM2_FLOATS (32768 + 4*512 + 272 + 4*64 + 32 + 32)
#define SMEM2_BYTES (SM2_FLOATS * 4)

__device__ __forceinline__ float blk_reduce(float v, float* red, bool domax) {
    const int lane = threadIdx.x & 31, wid = threadIdx.x >> 5;
    #pragma unroll
    for (int o = 16; o; o >>= 1) {
        float t = __shfl_xor_sync(0xffffffffu, v, o);
        v = domax ? fmaxf(v, t) : v + t;
    }
    if (lane == 0) red[wid] = v;
    __syncthreads();
    if (threadIdx.x < 32) {
        float t = (lane < 16) ? red[lane] : (domax ? -3.4e38f : 0.f);
        #pragma unroll
        for (int o = 8; o; o >>= 1) {
            float u = __shfl_xor_sync(0xffffffffu, t, o);
            t = domax ? fmaxf(t, u) : t + u;
        }
        if (lane == 0) red[16] = t;
    }
    __syncthreads();
    float r = red[16];
    __syncthreads();
    return r;
}

__global__ void __launch_bounds__(512, 1) ntm_update_kernel(
    const float* __restrict__ bank, const float* __restrict__ w_read,
    const float* __restrict__ w_write, const float* __restrict__ outW,
    const float* __restrict__ outb, float* __restrict__ d_out)
{
    extern __shared__ float sm[];
    float* bank_s = sm;                       // 32768
    float* cosR   = sm + 32768;               // 512
    float* cosW   = cosR + 512;               // 512
    float* wA     = cosW + 512;               // 512
    float* wB     = wA + 512;                 // 512
    float* pr     = wB + 512;                 // 272
    float* ktR    = pr + 272;                 // 64
    float* ktW    = ktR + 64;                 // 64
    float* dvec   = ktW + 64;                 // 64
    float* readv  = dvec + 64;                // 64
    float* red    = readv + 64;               // 32
    float* sc     = red + 32;                 // scalars
    // sc: 0 nKtR, 1 nKtW, 2 betaR, 3 gR, 4..6 smR, 7 gammaR,
    //     8 betaW, 9 gW, 10..12 smW, 13 gammaW

    const int tid = threadIdx.x;
    const int b   = blockIdx.x;

    // issue async bank load first (overlap with param math)
    {
        const float4* gsrc = (const float4*)(bank + (size_t)b * (NN * MM));
        uint32_t sbase = (uint32_t)__cvta_generic_to_shared(bank_s);
        #pragma unroll
        for (int k = 0; k < 16; ++k) {
            int j = tid + k * 512;
            asm volatile("cp.async.cg.shared.global [%0], [%1], 16;\n"
                         :: "r"(sbase + j * 16), "l"(gsrc + j));
        }
        asm volatile("cp.async.commit_group;\n");
    }

    // load repr params
    if (tid < RSZ) pr[tid] = g_repr[(size_t)b * RSZ + tid];
    __syncthreads();

    if (tid < 64) {
        ktR[tid]  = tanhf(pr[tid]);
        ktW[tid]  = tanhf(pr[PSZ + tid]);
        dvec[tid] = tanhf(pr[2 * PSZ + MM + tid]) - sigmf(pr[2 * PSZ + tid]);
    }
    if (tid == 64) { sc[2] = softplusf(pr[64]);  sc[3] = sigmf(pr[65]);  sc[7]  = softplusf(pr[69])  + 1.f; }
    if (tid == 65) { sc[8] = softplusf(pr[134]); sc[9] = sigmf(pr[135]); sc[13] = softplusf(pr[139]) + 1.f; }
    if (tid == 66) {
        float a0 = pr[66], a1 = pr[67], a2 = pr[68];
        float m = fmaxf(a0, fmaxf(a1, a2));
        float e0 = __expf(a0 - m), e1 = __expf(a1 - m), e2 = __expf(a2 - m);
        float s = e0 + e1 + e2;
        sc[4] = e0 / s; sc[5] = e1 / s; sc[6] = e2 / s;
    }
    if (tid == 67) {
        float a0 = pr[136], a1 = pr[137], a2 = pr[138];
        float m = fmaxf(a0, fmaxf(a1, a2));
        float e0 = __expf(a0 - m), e1 = __expf(a1 - m), e2 = __expf(a2 - m);
        float s = e0 + e1 + e2;
        sc[10] = e0 / s; sc[11] = e1 / s; sc[12] = e2 / s;
    }
    __syncthreads();

    // key norms (warps 0 and 1)
    if (tid < 32) {
        float v = ktR[tid] * ktR[tid] + ktR[tid + 32] * ktR[tid + 32];
        #pragma unroll
        for (int o = 16; o; o >>= 1) v += __shfl_xor_sync(0xffffffffu, v, o);
        if (tid == 0) sc[0] = sqrtf(v);
    } else if (tid < 64) {
        int l = tid - 32;
        float v = ktW[l] * ktW[l] + ktW[l + 32] * ktW[l + 32];
        #pragma unroll
        for (int o = 16; o; o >>= 1) v += __shfl_xor_sync(0xffffffffu, v, o);
        if (l == 0) sc[1] = sqrtf(v);
    }

    asm volatile("cp.async.wait_group 0;\n");
    __syncthreads();

    // cosine similarities (both keys in one smem pass)
    {
        const int wid = tid >> 5, lane = tid & 31;
        const float nR = sc[0], nW = sc[1];
        float2 kR2 = *(const float2*)&ktR[2 * lane];
        float2 kW2 = *(const float2*)&ktW[2 * lane];
        for (int n = wid; n < NN; n += 16) {
            float2 v = *(const float2*)&bank_s[n * MM + 2 * lane];
            float dR = v.x * kR2.x + v.y * kR2.y;
            float dW = v.x * kW2.x + v.y * kW2.y;
            float ss = v.x * v.x + v.y * v.y;
            #pragma unroll
            for (int o = 16; o; o >>= 1) {
                dR += __shfl_xor_sync(0xffffffffu, dR, o);
                dW += __shfl_xor_sync(0xffffffffu, dW, o);
                ss += __shfl_xor_sync(0xffffffffu, ss, o);
            }
            if (lane == 0) {
                float nb = sqrtf(ss);
                cosR[n] = dR / fmaxf(nb * nR, 1e-8f);
                cosW[n] = dW / fmaxf(nb * nW, 1e-8f);
            }
        }
    }
    __syncthreads();

    for (int pass = 0; pass < 2; ++pass) {
        const float* cosv = pass ? cosW : cosR;
        const float beta  = pass ? sc[8]  : sc[2];
        const float g     = pass ? sc[9]  : sc[3];
        const float sm0   = pass ? sc[10] : sc[4];
        const float sm1   = pass ? sc[11] : sc[5];
        const float sm2   = pass ? sc[12] : sc[6];
        const float gamma = pass ? sc[13] : sc[7];
        const float* wprev = (pass ? w_write : w_read) + (size_t)b * NN;

        float val = beta * cosv[tid];
        float mx  = blk_reduce(val, red, true);
        float e   = __expf(val - mx);
        float s   = blk_reduce(e, red, false);
        float wg  = g * (e / s) + (1.f - g) * wprev[tid];
        wA[tid] = wg;
        __syncthreads();
        float ws  = wA[(tid + NN - 1) & (NN - 1)] * sm0 + wg * sm1
                  + wA[(tid + 1) & (NN - 1)] * sm2;
        float wsh = __expf(gamma * __logf(fmaxf(ws, 1e-30f)));
        float ssum = blk_reduce(wsh, red, false);
        wB[tid] = wsh / ssum;
        __syncthreads();

        if (pass == 0) {
            // read vector: partial sums into cosR (consumed), then reduce
            int m = tid & 63, c = tid >> 6;
            float p = 0.f;
            int nbase = c * 64;
            #pragma unroll 4
            for (int n = nbase; n < nbase + 64; ++n)
                p += wB[n] * bank_s[n * MM + m];
            cosR[tid] = p;
            __syncthreads();
            if (tid < 64) {
                float r = 0.f;
                #pragma unroll
                for (int cc = 0; cc < 8; ++cc) r += cosR[cc * 64 + tid];
                readv[tid] = r;
            }
            __syncthreads();
        } else {
            // new_bank = bank + ww[n] * (a - e)[m]
            float4* outp = (float4*)(d_out + (size_t)BB * SEQW + (size_t)b * (NN * MM));
            #pragma unroll 4
            for (int j = tid; j < (NN * MM) / 4; j += 512) {
                int n  = j >> 4;
                int m0 = (j & 15) * 4;
                float4 v  = *(const float4*)&bank_s[j * 4];
                float  w  = wB[n];
                float4 dv = *(const float4*)&dvec[m0];
                v.x += w * dv.x; v.y += w * dv.y;
                v.z += w * dv.z; v.w += w * dv.w;
                outp[j] = v;
            }
        }
    }

    // epilogue: seq_out[b, o] = sigmoid([ctrl_out, read] @ outW + outb)
    if (tid < 256) {
        const int o = tid >> 5, l = tid & 31;
        float a = 0.f;
        #pragma unroll
        for (int i = l; i < COUT + MM; i += 32) {
            float xi = (i < COUT) ? g_ctrl[(size_t)b * COUT + i] : readv[i - COUT];
            a += xi * outW[i * SEQW + o];
        }
        #pragma unroll
        for (int off = 16; off; off >>= 1) a += __shfl_xor_sync(0xffffffffu, a, off);
        if (l == 0) d_out[(size_t)b * SEQW + o] = sigmf(a + outb[o]);
    }
}

// ---------------------------------------------------------------------------
extern "C" void kernel_launch(void* const* d_in, const int* in_sizes, int n_in,
                              void* d_out, int out_size)
{
    const float* x         = (const float*)d_in[0];
    const float* prev_read = (const float*)d_in[1];
    const float* bank      = (const float*)d_in[2];
    const float* w_read    = (const float*)d_in[3];
    const float* w_write   = (const float*)d_in[4];
    const float* W0        = (const float*)d_in[5];
    const float* b0        = (const float*)d_in[6];
    const float* W1        = (const float*)d_in[7];
    const float* b1        = (const float*)d_in[8];
    const float* Wout      = (const float*)d_in[9];
    const float* bout      = (const float*)d_in[10];
    const float* reprW     = (const float*)d_in[11];
    const float* reprb     = (const float*)d_in[12];
    const float* outW      = (const float*)d_in[13];
    const float* outb      = (const float*)d_in[14];
    float* out = (float*)d_out;

    cudaFuncSetAttribute(ctrl_kernel,
                         cudaFuncAttributeMaxDynamicSharedMemorySize, SMEM1_BYTES);
    cudaFuncSetAttribute(ntm_update_kernel,
                         cudaFuncAttributeMaxDynamicSharedMemorySize, SMEM2_BYTES);

    ctrl_kernel<<<BB / TB, 256, SMEM1_BYTES>>>(x, prev_read, W0, b0, W1, b1,
                                               Wout, bout, reprW, reprb);
    ntm_update_kernel<<<BB, 512, SMEM2_BYTES>>>(bank, w_read, w_write,
                                                outW, outb, out);
}

// round 6
// speedup vs baseline: 1.0067x; 1.0067x over previous
#include <cuda_runtime.h>
#include <cstdint>

// Problem constants
#define BB   4096
#define NN   512
#define MM   64
#define SEQW 8
#define HID  256
#define COUT 128
#define INSZ 73          // SEQW+1 + MM
#define PSZ  70          // M + 1 + 1 + 3 + 1
#define RSZ  268         // 2*PSZ + 2*M

// scratch (device globals: no allocation allowed)
__device__ float g_repr[BB * RSZ];
__device__ float g_ctrl[BB * COUT];

__device__ __forceinline__ float softplusf(float x) {
    return fmaxf(x, 0.f) + log1pf(expf(-fabsf(x)));
}
__device__ __forceinline__ float sigmf(float x) {
    return 1.f / (1.f + __expf(-x));
}
__device__ __forceinline__ float leakyf(float x) {
    return x > 0.f ? x : 0.01f * x;
}

// ---------------------------------------------------------------------------
// Kernel 1: controller MLP. 16 batch rows per CTA, 256 threads, 256 CTAs.
// Activations transposed in smem with stride 20 (conflict-free float4 I/O).
// 3 CTAs/SM for latency hiding.
// ---------------------------------------------------------------------------
#define TB  16
#define AST 20

__global__ void __launch_bounds__(256, 3) ctrl_kernel(
    const float* __restrict__ x, const float* __restrict__ prev_read,
    const float* __restrict__ W0, const float* __restrict__ b0,
    const float* __restrict__ W1, const float* __restrict__ b1,
    const float* __restrict__ Wout, const float* __restrict__ bout,
    const float* __restrict__ reprW, const float* __restrict__ reprb)
{
    __shared__ float A[256 * AST];
    __shared__ float Bf[256 * AST];
    const int tid = threadIdx.x;
    const int r0  = blockIdx.x * TB;

    // load ctrl_in transposed: A[i*AST + r]
    for (int idx = tid; idx < INSZ * TB; idx += 256) {
        int i = idx >> 4, r = idx & 15;
        float v = (i < SEQW + 1) ? x[(size_t)(r0 + r) * (SEQW + 1) + i]
                                 : prev_read[(size_t)(r0 + r) * MM + (i - SEQW - 1)];
        A[i * AST + r] = v;
    }
    __syncthreads();

    // layer 1: INSZ -> 256, A -> Bf
    {
        const int j = tid;
        float4 acc[4];
        #pragma unroll
        for (int q = 0; q < 4; ++q) acc[q] = make_float4(0.f, 0.f, 0.f, 0.f);
        for (int i = 0; i < INSZ; ++i) {
            float w = W0[i * 256 + j];
            const float4* src = (const float4*)&A[i * AST];
            #pragma unroll
            for (int q = 0; q < 4; ++q) {
                float4 v = src[q];
                acc[q].x += w * v.x; acc[q].y += w * v.y;
                acc[q].z += w * v.z; acc[q].w += w * v.w;
            }
        }
        float bb = b0[j];
        float4* dst = (float4*)&Bf[j * AST];
        #pragma unroll
        for (int q = 0; q < 4; ++q) {
            float4 v = acc[q];
            v.x = leakyf(v.x + bb); v.y = leakyf(v.y + bb);
            v.z = leakyf(v.z + bb); v.w = leakyf(v.w + bb);
            dst[q] = v;
        }
    }
    __syncthreads();

    // layer 2: 256 -> 256, Bf -> A
    {
        const int j = tid;
        float4 acc[4];
        #pragma unroll
        for (int q = 0; q < 4; ++q) acc[q] = make_float4(0.f, 0.f, 0.f, 0.f);
        for (int i = 0; i < HID; ++i) {
            float w = W1[i * 256 + j];
            const float4* src = (const float4*)&Bf[i * AST];
            #pragma unroll
            for (int q = 0; q < 4; ++q) {
                float4 v = src[q];
                acc[q].x += w * v.x; acc[q].y += w * v.y;
                acc[q].z += w * v.z; acc[q].w += w * v.w;
            }
        }
        float bb = b1[j];
        float4* dst = (float4*)&A[j * AST];
        #pragma unroll
        for (int q = 0; q < 4; ++q) {
            float4 v = acc[q];
            v.x = leakyf(v.x + bb); v.y = leakyf(v.y + bb);
            v.z = leakyf(v.z + bb); v.w = leakyf(v.w + bb);
            dst[q] = v;
        }
    }
    __syncthreads();

    // layer 3: 256 -> 128 (tanh), A -> Bf, also write g_ctrl
    if (tid < COUT) {
        const int j = tid;
        float4 acc[4];
        #pragma unroll
        for (int q = 0; q < 4; ++q) acc[q] = make_float4(0.f, 0.f, 0.f, 0.f);
        for (int i = 0; i < HID; ++i) {
            float w = Wout[i * COUT + j];
            const float4* src = (const float4*)&A[i * AST];
            #pragma unroll
            for (int q = 0; q < 4; ++q) {
                float4 v = src[q];
                acc[q].x += w * v.x; acc[q].y += w * v.y;
                acc[q].z += w * v.z; acc[q].w += w * v.w;
            }
        }
        float bb = bout[j];
        #pragma unroll
        for (int q = 0; q < 4; ++q) {
            float4 v = acc[q];
            v.x = tanhf(v.x + bb); v.y = tanhf(v.y + bb);
            v.z = tanhf(v.z + bb); v.w = tanhf(v.w + bb);
            ((float4*)&Bf[j * AST])[q] = v;
            g_ctrl[(size_t)(r0 + q * 4 + 0) * COUT + j] = v.x;
            g_ctrl[(size_t)(r0 + q * 4 + 1) * COUT + j] = v.y;
            g_ctrl[(size_t)(r0 + q * 4 + 2) * COUT + j] = v.z;
            g_ctrl[(size_t)(r0 + q * 4 + 3) * COUT + j] = v.w;
        }
    }
    __syncthreads();

    // layer 4: 128 -> 268 (repr), Bf -> g_repr
    for (int o = tid; o < RSZ; o += 256) {
        float4 acc[4];
        #pragma unroll
        for (int q = 0; q < 4; ++q) acc[q] = make_float4(0.f, 0.f, 0.f, 0.f);
        for (int i = 0; i < COUT; ++i) {
            float w = reprW[i * RSZ + o];
            const float4* src = (const float4*)&Bf[i * AST];
            #pragma unroll
            for (int q = 0; q < 4; ++q) {
                float4 v = src[q];
                acc[q].x += w * v.x; acc[q].y += w * v.y;
                acc[q].z += w * v.z; acc[q].w += w * v.w;
            }
        }
        float bb = reprb[o];
        #pragma unroll
        for (int q = 0; q < 4; ++q) {
            g_repr[(size_t)(r0 + q * 4 + 0) * RSZ + o] = acc[q].x + bb;
            g_repr[(size_t)(r0 + q * 4 + 1) * RSZ + o] = acc[q].y + bb;
            g_repr[(size_t)(r0 + q * 4 + 2) * RSZ + o] = acc[q].z + bb;
            g_repr[(size_t)(r0 + q * 4 + 3) * RSZ + o] = acc[q].w + bb;
        }
    }
}

// ---------------------------------------------------------------------------
// Kernel 2: per-batch-row addressing + memory read + bank update + seq_out.
// No smem bank staging: pass A reads bank from DRAM (dots+norms), pass B
// re-reads it (L2 hit) for fused read-vector + erase/add write. ~15 KB smem,
// 2 CTAs/SM for cross-CTA phase overlap.
// ---------------------------------------------------------------------------
__device__ __forceinline__ float blk_reduce(float v, float* red, bool domax) {
    const int lane = threadIdx.x & 31, wid = threadIdx.x >> 5;
    #pragma unroll
    for (int o = 16; o; o >>= 1) {
        float t = __shfl_xor_sync(0xffffffffu, v, o);
        v = domax ? fmaxf(v, t) : v + t;
    }
    if (lane == 0) red[wid] = v;
    __syncthreads();
    if (threadIdx.x < 32) {
        float t = (lane < 16) ? red[lane] : (domax ? -3.4e38f : 0.f);
        #pragma unroll
        for (int o = 8; o; o >>= 1) {
            float u = __shfl_xor_sync(0xffffffffu, t, o);
            t = domax ? fmaxf(t, u) : t + u;
        }
        if (lane == 0) red[16] = t;
    }
    __syncthreads();
    float r = red[16];
    __syncthreads();
    return r;
}

__global__ void __launch_bounds__(512, 2) ntm_update_kernel(
    const float* __restrict__ bank, const float* __restrict__ w_read,
    const float* __restrict__ w_write, const float* __restrict__ outW,
    const float* __restrict__ outb, float* __restrict__ d_out)
{
    __shared__ float cosR[512];
    __shared__ float cosW[512];
    __shared__ float wr_s[512];       // final read weights
    __shared__ float ww_s[512];       // final write weights (+ scratch wA)
    __shared__ float wA[512];         // gated weights scratch
    __shared__ float part[16 * 64];   // per-warp read-vector partials
    __shared__ float pr[RSZ];
    __shared__ float ktR[64], ktW[64], dvec[64], readv[64];
    __shared__ float red[32];
    __shared__ float sc[16];
    // sc: 0 nKtR, 1 nKtW, 2 betaR, 3 gR, 4..6 smR, 7 gammaR,
    //     8 betaW, 9 gW, 10..12 smW, 13 gammaW

    const int tid  = threadIdx.x;
    const int b    = blockIdx.x;
    const int wid  = tid >> 5, lane = tid & 31;
    const float* bank_b = bank + (size_t)b * (NN * MM);

    // load repr params
    if (tid < RSZ) pr[tid] = g_repr[(size_t)b * RSZ + tid];
    __syncthreads();

    if (tid < 64) {
        ktR[tid]  = tanhf(pr[tid]);
        ktW[tid]  = tanhf(pr[PSZ + tid]);
        dvec[tid] = tanhf(pr[2 * PSZ + MM + tid]) - sigmf(pr[2 * PSZ + tid]);
    }
    if (tid == 64) { sc[2] = softplusf(pr[64]);  sc[3] = sigmf(pr[65]);  sc[7]  = softplusf(pr[69])  + 1.f; }
    if (tid == 65) { sc[8] = softplusf(pr[134]); sc[9] = sigmf(pr[135]); sc[13] = softplusf(pr[139]) + 1.f; }
    if (tid == 66) {
        float a0 = pr[66], a1 = pr[67], a2 = pr[68];
        float m = fmaxf(a0, fmaxf(a1, a2));
        float e0 = __expf(a0 - m), e1 = __expf(a1 - m), e2 = __expf(a2 - m);
        float s = e0 + e1 + e2;
        sc[4] = e0 / s; sc[5] = e1 / s; sc[6] = e2 / s;
    }
    if (tid == 67) {
        float a0 = pr[136], a1 = pr[137], a2 = pr[138];
        float m = fmaxf(a0, fmaxf(a1, a2));
        float e0 = __expf(a0 - m), e1 = __expf(a1 - m), e2 = __expf(a2 - m);
        float s = e0 + e1 + e2;
        sc[10] = e0 / s; sc[11] = e1 / s; sc[12] = e2 / s;
    }
    __syncthreads();

    // key norms (warps 0 and 1)
    if (tid < 32) {
        float v = ktR[tid] * ktR[tid] + ktR[tid + 32] * ktR[tid + 32];
        #pragma unroll
        for (int o = 16; o; o >>= 1) v += __shfl_xor_sync(0xffffffffu, v, o);
        if (tid == 0) sc[0] = sqrtf(v);
    } else if (tid < 64) {
        int l = tid - 32;
        float v = ktW[l] * ktW[l] + ktW[l + 32] * ktW[l + 32];
        #pragma unroll
        for (int o = 16; o; o >>= 1) v += __shfl_xor_sync(0xffffffffu, v, o);
        if (l == 0) sc[1] = sqrtf(v);
    }
    __syncthreads();

    // ── Pass A: cosine similarities, one warp per row, rows strided by 16.
    {
        const float nR = sc[0], nW = sc[1];
        const float2 kR2 = *(const float2*)&ktR[2 * lane];
        const float2 kW2 = *(const float2*)&ktW[2 * lane];
        #pragma unroll 2
        for (int n = wid; n < NN; n += 16) {
            float2 v = *(const float2*)(bank_b + n * MM + 2 * lane);
            float dR = v.x * kR2.x + v.y * kR2.y;
            float dW = v.x * kW2.x + v.y * kW2.y;
            float ss = v.x * v.x + v.y * v.y;
            #pragma unroll
            for (int o = 16; o; o >>= 1) {
                dR += __shfl_xor_sync(0xffffffffu, dR, o);
                dW += __shfl_xor_sync(0xffffffffu, dW, o);
                ss += __shfl_xor_sync(0xffffffffu, ss, o);
            }
            if (lane == 0) {
                float nb = sqrtf(ss);
                cosR[n] = dR / fmaxf(nb * nR, 1e-8f);
                cosW[n] = dW / fmaxf(nb * nW, 1e-8f);
            }
        }
    }
    __syncthreads();

    // ── Addressing weight math (thread-per-n), both heads.
    for (int pass = 0; pass < 2; ++pass) {
        const float* cosv = pass ? cosW : cosR;
        const float beta  = pass ? sc[8]  : sc[2];
        const float g     = pass ? sc[9]  : sc[3];
        const float sm0   = pass ? sc[10] : sc[4];
        const float sm1   = pass ? sc[11] : sc[5];
        const float sm2   = pass ? sc[12] : sc[6];
        const float gamma = pass ? sc[13] : sc[7];
        const float* wprev = (pass ? w_write : w_read) + (size_t)b * NN;

        float val = beta * cosv[tid];
        float mx  = blk_reduce(val, red, true);
        float e   = __expf(val - mx);
        float s   = blk_reduce(e, red, false);
        float wg  = g * (e / s) + (1.f - g) * wprev[tid];
        wA[tid] = wg;
        __syncthreads();
        float ws  = wA[(tid + NN - 1) & (NN - 1)] * sm0 + wg * sm1
                  + wA[(tid + 1) & (NN - 1)] * sm2;
        float wsh = __expf(gamma * __logf(fmaxf(ws, 1e-30f)));
        float ssum = blk_reduce(wsh, red, false);
        if (pass == 0) wr_s[tid] = wsh / ssum;
        else           ww_s[tid] = wsh / ssum;
        __syncthreads();
    }

    // ── Pass B: fused read-vector + erase/add bank update (bank re-read, L2).
    {
        float* outp = d_out + (size_t)BB * SEQW + (size_t)b * (NN * MM);
        const float2 dv2 = *(const float2*)&dvec[2 * lane];
        float2 racc = make_float2(0.f, 0.f);
        #pragma unroll 2
        for (int n = wid; n < NN; n += 16) {
            float2 v = *(const float2*)(bank_b + n * MM + 2 * lane);
            float wwn = ww_s[n];
            float wrn = wr_s[n];
            racc.x += wrn * v.x;
            racc.y += wrn * v.y;
            float2 o;
            o.x = v.x + wwn * dv2.x;
            o.y = v.y + wwn * dv2.y;
            *(float2*)(outp + n * MM + 2 * lane) = o;
        }
        *(float2*)&part[wid * 64 + 2 * lane] = racc;
    }
    __syncthreads();
    if (tid < 64) {
        float r = 0.f;
        #pragma unroll
        for (int w = 0; w < 16; ++w) r += part[w * 64 + tid];
        readv[tid] = r;
    }
    __syncthreads();

    // ── Epilogue: seq_out[b, o] = sigmoid([ctrl_out, read] @ outW + outb)
    if (tid < 256) {
        const int o = tid >> 5, l = tid & 31;
        float a = 0.f;
        #pragma unroll
        for (int i = l; i < COUT + MM; i += 32) {
            float xi = (i < COUT) ? g_ctrl[(size_t)b * COUT + i] : readv[i - COUT];
            a += xi * outW[i * SEQW + o];
        }
        #pragma unroll
        for (int off = 16; off; off >>= 1) a += __shfl_xor_sync(0xffffffffu, a, off);
        if (l == 0) d_out[(size_t)b * SEQW + o] = sigmf(a + outb[o]);
    }
}

// ---------------------------------------------------------------------------
extern "C" void kernel_launch(void* const* d_in, const int* in_sizes, int n_in,
                              void* d_out, int out_size)
{
    const float* x         = (const float*)d_in[0];
    const float* prev_read = (const float*)d_in[1];
    const float* bank      = (const float*)d_in[2];
    const float* w_read    = (const float*)d_in[3];
    const float* w_write   = (const float*)d_in[4];
    const float* W0        = (const float*)d_in[5];
    const float* b0        = (const float*)d_in[6];
    const float* W1        = (const float*)d_in[7];
    const float* b1        = (const float*)d_in[8];
    const float* Wout      = (const float*)d_in[9];
    const float* bout      = (const float*)d_in[10];
    const float* reprW     = (const float*)d_in[11];
    const float* reprb     = (const float*)d_in[12];
    const float* outW      = (const float*)d_in[13];
    const float* outb      = (const float*)d_in[14];
    float* out = (float*)d_out;

    ctrl_kernel<<<BB / TB, 256>>>(x, prev_read, W0, b0, W1, b1,
                                  Wout, bout, reprW, reprb);
    ntm_update_kernel<<<BB, 512>>>(bank, w_read, w_write, outW, outb, out);
}

// round 7
// speedup vs baseline: 1.7313x; 1.7198x over previous
#include <cuda_runtime.h>
#include <cstdint>

// Problem constants
#define BB   4096
#define NN   512
#define MM   64
#define SEQW 8
#define HID  256
#define COUT 128
#define INSZ 73          // SEQW+1 + MM
#define PSZ  70          // M + 1 + 1 + 3 + 1
#define RSZ  268         // 2*PSZ + 2*M

// scratch (device globals: no allocation allowed)
__device__ float g_repr[BB * RSZ];
__device__ float g_ctrl[BB * COUT];

__device__ __forceinline__ float softplusf(float x) {
    return fmaxf(x, 0.f) + log1pf(expf(-fabsf(x)));
}
__device__ __forceinline__ float sigmf(float x) {
    return 1.f / (1.f + __expf(-x));
}
__device__ __forceinline__ float leakyf(float x) {
    return x > 0.f ? x : 0.01f * x;
}

// ---------------------------------------------------------------------------
// Kernel 1: controller MLP (unchanged from round 5).
// ---------------------------------------------------------------------------
#define TB  16
#define AST 20

__global__ void __launch_bounds__(256, 3) ctrl_kernel(
    const float* __restrict__ x, const float* __restrict__ prev_read,
    const float* __restrict__ W0, const float* __restrict__ b0,
    const float* __restrict__ W1, const float* __restrict__ b1,
    const float* __restrict__ Wout, const float* __restrict__ bout,
    const float* __restrict__ reprW, const float* __restrict__ reprb)
{
    __shared__ float A[256 * AST];
    __shared__ float Bf[256 * AST];
    const int tid = threadIdx.x;
    const int r0  = blockIdx.x * TB;

    for (int idx = tid; idx < INSZ * TB; idx += 256) {
        int i = idx >> 4, r = idx & 15;
        float v = (i < SEQW + 1) ? x[(size_t)(r0 + r) * (SEQW + 1) + i]
                                 : prev_read[(size_t)(r0 + r) * MM + (i - SEQW - 1)];
        A[i * AST + r] = v;
    }
    __syncthreads();

    // layer 1: INSZ -> 256, A -> Bf
    {
        const int j = tid;
        float4 acc[4];
        #pragma unroll
        for (int q = 0; q < 4; ++q) acc[q] = make_float4(0.f, 0.f, 0.f, 0.f);
        for (int i = 0; i < INSZ; ++i) {
            float w = W0[i * 256 + j];
            const float4* src = (const float4*)&A[i * AST];
            #pragma unroll
            for (int q = 0; q < 4; ++q) {
                float4 v = src[q];
                acc[q].x += w * v.x; acc[q].y += w * v.y;
                acc[q].z += w * v.z; acc[q].w += w * v.w;
            }
        }
        float bb = b0[j];
        float4* dst = (float4*)&Bf[j * AST];
        #pragma unroll
        for (int q = 0; q < 4; ++q) {
            float4 v = acc[q];
            v.x = leakyf(v.x + bb); v.y = leakyf(v.y + bb);
            v.z = leakyf(v.z + bb); v.w = leakyf(v.w + bb);
            dst[q] = v;
        }
    }
    __syncthreads();

    // layer 2: 256 -> 256, Bf -> A
    {
        const int j = tid;
        float4 acc[4];
        #pragma unroll
        for (int q = 0; q < 4; ++q) acc[q] = make_float4(0.f, 0.f, 0.f, 0.f);
        for (int i = 0; i < HID; ++i) {
            float w = W1[i * 256 + j];
            const float4* src = (const float4*)&Bf[i * AST];
            #pragma unroll
            for (int q = 0; q < 4; ++q) {
                float4 v = src[q];
                acc[q].x += w * v.x; acc[q].y += w * v.y;
                acc[q].z += w * v.z; acc[q].w += w * v.w;
            }
        }
        float bb = b1[j];
        float4* dst = (float4*)&A[j * AST];
        #pragma unroll
        for (int q = 0; q < 4; ++q) {
            float4 v = acc[q];
            v.x = leakyf(v.x + bb); v.y = leakyf(v.y + bb);
            v.z = leakyf(v.z + bb); v.w = leakyf(v.w + bb);
            dst[q] = v;
        }
    }
    __syncthreads();

    // layer 3: 256 -> 128 (tanh), A -> Bf, also write g_ctrl
    if (tid < COUT) {
        const int j = tid;
        float4 acc[4];
        #pragma unroll
        for (int q = 0; q < 4; ++q) acc[q] = make_float4(0.f, 0.f, 0.f, 0.f);
        for (int i = 0; i < HID; ++i) {
            float w = Wout[i * COUT + j];
            const float4* src = (const float4*)&A[i * AST];
            #pragma unroll
            for (int q = 0; q < 4; ++q) {
                float4 v = src[q];
                acc[q].x += w * v.x; acc[q].y += w * v.y;
                acc[q].z += w * v.z; acc[q].w += w * v.w;
            }
        }
        float bb = bout[j];
        #pragma unroll
        for (int q = 0; q < 4; ++q) {
            float4 v = acc[q];
            v.x = tanhf(v.x + bb); v.y = tanhf(v.y + bb);
            v.z = tanhf(v.z + bb); v.w = tanhf(v.w + bb);
            ((float4*)&Bf[j * AST])[q] = v;
            g_ctrl[(size_t)(r0 + q * 4 + 0) * COUT + j] = v.x;
            g_ctrl[(size_t)(r0 + q * 4 + 1) * COUT + j] = v.y;
            g_ctrl[(size_t)(r0 + q * 4 + 2) * COUT + j] = v.z;
            g_ctrl[(size_t)(r0 + q * 4 + 3) * COUT + j] = v.w;
        }
    }
    __syncthreads();

    // layer 4: 128 -> 268 (repr), Bf -> g_repr
    for (int o = tid; o < RSZ; o += 256) {
        float4 acc[4];
        #pragma unroll
        for (int q = 0; q < 4; ++q) acc[q] = make_float4(0.f, 0.f, 0.f, 0.f);
        for (int i = 0; i < COUT; ++i) {
            float w = reprW[i * RSZ + o];
            const float4* src = (const float4*)&Bf[i * AST];
            #pragma unroll
            for (int q = 0; q < 4; ++q) {
                float4 v = src[q];
                acc[q].x += w * v.x; acc[q].y += w * v.y;
                acc[q].z += w * v.z; acc[q].w += w * v.w;
            }
        }
        float bb = reprb[o];
        #pragma unroll
        for (int q = 0; q < 4; ++q) {
            g_repr[(size_t)(r0 + q * 4 + 0) * RSZ + o] = acc[q].x + bb;
            g_repr[(size_t)(r0 + q * 4 + 1) * RSZ + o] = acc[q].y + bb;
            g_repr[(size_t)(r0 + q * 4 + 2) * RSZ + o] = acc[q].z + bb;
            g_repr[(size_t)(r0 + q * 4 + 3) * RSZ + o] = acc[q].w + bb;
        }
    }
}

// ---------------------------------------------------------------------------
// Kernel 2: addressing + read + bank update + seq_out.
// 4 rows per warp / 8 lanes per row / float4 lanes: shuffle count cut ~6x.
// Fused dual-head block reductions (float2), analytic softmax shift (no max
// reduce), front-loaded prefetch of all small operands.
// ---------------------------------------------------------------------------
__device__ __forceinline__ float2 blk_sum2(float2 v, float2* red) {
    const int lane = threadIdx.x & 31, wid = threadIdx.x >> 5;
    #pragma unroll
    for (int o = 16; o; o >>= 1) {
        v.x += __shfl_xor_sync(0xffffffffu, v.x, o);
        v.y += __shfl_xor_sync(0xffffffffu, v.y, o);
    }
    if (lane == 0) red[wid] = v;
    __syncthreads();
    if (threadIdx.x < 32) {
        float2 t = (lane < 16) ? red[lane] : make_float2(0.f, 0.f);
        #pragma unroll
        for (int o = 8; o; o >>= 1) {
            t.x += __shfl_xor_sync(0xffffffffu, t.x, o);
            t.y += __shfl_xor_sync(0xffffffffu, t.y, o);
        }
        if (lane == 0) red[16] = t;
    }
    __syncthreads();
    float2 r = red[16];
    __syncthreads();
    return r;
}

__global__ void __launch_bounds__(512, 2) ntm_update_kernel(
    const float* __restrict__ bank, const float* __restrict__ w_read,
    const float* __restrict__ w_write, const float* __restrict__ outW,
    const float* __restrict__ outb, float* __restrict__ d_out)
{
    __shared__ float cosR[512], cosW[512];
    __shared__ float wA[512], wB[512];
    __shared__ float wr_s[512], ww_s[512];
    __shared__ float part[16 * 64];
    __shared__ float pr[RSZ];
    __shared__ float ktR[64], ktW[64], dvec[64], readv[64];
    __shared__ float sCtrl[COUT];
    __shared__ float sOutW[(COUT + MM) * SEQW];
    __shared__ float sOutB[SEQW];
    __shared__ float2 red2[17];
    __shared__ float sc[16];
    // sc: 0 nKtR, 1 nKtW, 2 betaR, 3 gR, 4..6 smR, 7 gammaR,
    //     8 betaW, 9 gW, 10..12 smW, 13 gammaW

    const int tid  = threadIdx.x;
    const int b    = blockIdx.x;
    const int wid  = tid >> 5, lane = tid & 31;
    const int r    = lane >> 3;        // row within 4-row group (0..3)
    const int h    = lane & 7;         // 8 lanes per row
    const float* bank_b = bank + (size_t)b * (NN * MM);

    // ── Front-loaded prefetch of all small operands (independent LDGs).
    float wprevR = w_read[(size_t)b * NN + tid];
    float wprevW = w_write[(size_t)b * NN + tid];
    if (tid < RSZ) pr[tid] = g_repr[(size_t)b * RSZ + tid];
    if (tid < COUT) sCtrl[tid] = g_ctrl[(size_t)b * COUT + tid];
    #pragma unroll
    for (int i = tid; i < (COUT + MM) * SEQW; i += 512) sOutW[i] = outW[i];
    if (tid < SEQW) sOutB[tid] = outb[tid];
    __syncthreads();

    if (tid < 64) {
        ktR[tid]  = tanhf(pr[tid]);
        ktW[tid]  = tanhf(pr[PSZ + tid]);
        dvec[tid] = tanhf(pr[2 * PSZ + MM + tid]) - sigmf(pr[2 * PSZ + tid]);
    }
    if (tid == 64) { sc[2] = softplusf(pr[64]);  sc[3] = sigmf(pr[65]);  sc[7]  = softplusf(pr[69])  + 1.f; }
    if (tid == 65) { sc[8] = softplusf(pr[134]); sc[9] = sigmf(pr[135]); sc[13] = softplusf(pr[139]) + 1.f; }
    if (tid == 66) {
        float a0 = pr[66], a1 = pr[67], a2 = pr[68];
        float m = fmaxf(a0, fmaxf(a1, a2));
        float e0 = __expf(a0 - m), e1 = __expf(a1 - m), e2 = __expf(a2 - m);
        float s = e0 + e1 + e2;
        sc[4] = e0 / s; sc[5] = e1 / s; sc[6] = e2 / s;
    }
    if (tid == 67) {
        float a0 = pr[136], a1 = pr[137], a2 = pr[138];
        float m = fmaxf(a0, fmaxf(a1, a2));
        float e0 = __expf(a0 - m), e1 = __expf(a1 - m), e2 = __expf(a2 - m);
        float s = e0 + e1 + e2;
        sc[10] = e0 / s; sc[11] = e1 / s; sc[12] = e2 / s;
    }
    __syncthreads();

    // key norms (warps 0 and 1)
    if (tid < 32) {
        float v = ktR[tid] * ktR[tid] + ktR[tid + 32] * ktR[tid + 32];
        #pragma unroll
        for (int o = 16; o; o >>= 1) v += __shfl_xor_sync(0xffffffffu, v, o);
        if (tid == 0) sc[0] = sqrtf(v);
    } else if (tid < 64) {
        int l = tid - 32;
        float v = ktW[l] * ktW[l] + ktW[l + 32] * ktW[l + 32];
        #pragma unroll
        for (int o = 16; o; o >>= 1) v += __shfl_xor_sync(0xffffffffu, v, o);
        if (l == 0) sc[1] = sqrtf(v);
    }
    __syncthreads();

    // ── Pass A: cosine similarities. 4 rows/warp, 8 lanes/row, float4 lanes.
    {
        const float nR = sc[0], nW = sc[1];
        const float4 kR0 = *(const float4*)&ktR[h * 4];
        const float4 kR1 = *(const float4*)&ktR[32 + h * 4];
        const float4 kW0 = *(const float4*)&ktW[h * 4];
        const float4 kW1 = *(const float4*)&ktW[32 + h * 4];
        #pragma unroll
        for (int step = 0; step < 8; ++step) {
            const int n = step * 64 + wid * 4 + r;
            const float* row = bank_b + n * MM;
            float4 v0 = *(const float4*)(row + h * 4);
            float4 v1 = *(const float4*)(row + 32 + h * 4);
            float dR = v0.x * kR0.x + v0.y * kR0.y + v0.z * kR0.z + v0.w * kR0.w
                     + v1.x * kR1.x + v1.y * kR1.y + v1.z * kR1.z + v1.w * kR1.w;
            float dW = v0.x * kW0.x + v0.y * kW0.y + v0.z * kW0.z + v0.w * kW0.w
                     + v1.x * kW1.x + v1.y * kW1.y + v1.z * kW1.z + v1.w * kW1.w;
            float ss = v0.x * v0.x + v0.y * v0.y + v0.z * v0.z + v0.w * v0.w
                     + v1.x * v1.x + v1.y * v1.y + v1.z * v1.z + v1.w * v1.w;
            #pragma unroll
            for (int o = 4; o; o >>= 1) {
                dR += __shfl_xor_sync(0xffffffffu, dR, o);
                dW += __shfl_xor_sync(0xffffffffu, dW, o);
                ss += __shfl_xor_sync(0xffffffffu, ss, o);
            }
            if (h == 0) {
                float nb = sqrtf(ss);
                cosR[n] = dR / fmaxf(nb * nR, 1e-8f);
                cosW[n] = dW / fmaxf(nb * nW, 1e-8f);
            }
        }
    }
    __syncthreads();

    // ── Addressing: both heads fused, thread-per-n.
    {
        const float betaR = sc[2], gR = sc[3], gammaR = sc[7];
        const float betaW = sc[8], gW = sc[9], gammaW = sc[13];
        // analytic shift: softmax(beta*cos) == exp(beta*(cos-1)) / sum
        float eR = __expf(betaR * (cosR[tid] - 1.f));
        float eW = __expf(betaW * (cosW[tid] - 1.f));
        float2 s = blk_sum2(make_float2(eR, eW), red2);
        float wgR = gR * (eR / s.x) + (1.f - gR) * wprevR;
        float wgW = gW * (eW / s.y) + (1.f - gW) * wprevW;
        wA[tid] = wgR; wB[tid] = wgW;
        __syncthreads();
        const int nm1 = (tid + NN - 1) & (NN - 1), np1 = (tid + 1) & (NN - 1);
        float wsR = wA[nm1] * sc[4] + wgR * sc[5] + wA[np1] * sc[6];
        float wsW = wB[nm1] * sc[10] + wgW * sc[11] + wB[np1] * sc[12];
        float wshR = __expf(gammaR * __logf(fmaxf(wsR, 1e-30f)));
        float wshW = __expf(gammaW * __logf(fmaxf(wsW, 1e-30f)));
        float2 s2 = blk_sum2(make_float2(wshR, wshW), red2);
        wr_s[tid] = wshR / s2.x;
        ww_s[tid] = wshW / s2.y;
    }
    __syncthreads();

    // ── Pass B: fused read-vector + erase/add bank update.
    {
        const float4 dv0 = *(const float4*)&dvec[h * 4];
        const float4 dv1 = *(const float4*)&dvec[32 + h * 4];
        float* outp = d_out + (size_t)BB * SEQW + (size_t)b * (NN * MM);
        float4 racc0 = make_float4(0.f, 0.f, 0.f, 0.f);
        float4 racc1 = make_float4(0.f, 0.f, 0.f, 0.f);
        #pragma unroll
        for (int step = 0; step < 8; ++step) {
            const int n = step * 64 + wid * 4 + r;
            const float* row = bank_b + n * MM;
            float4 v0 = *(const float4*)(row + h * 4);
            float4 v1 = *(const float4*)(row + 32 + h * 4);
            float wwn = ww_s[n];
            float wrn = wr_s[n];
            racc0.x += wrn * v0.x; racc0.y += wrn * v0.y;
            racc0.z += wrn * v0.z; racc0.w += wrn * v0.w;
            racc1.x += wrn * v1.x; racc1.y += wrn * v1.y;
            racc1.z += wrn * v1.z; racc1.w += wrn * v1.w;
            float4 o0, o1;
            o0.x = v0.x + wwn * dv0.x; o0.y = v0.y + wwn * dv0.y;
            o0.z = v0.z + wwn * dv0.z; o0.w = v0.w + wwn * dv0.w;
            o1.x = v1.x + wwn * dv1.x; o1.y = v1.y + wwn * dv1.y;
            o1.z = v1.z + wwn * dv1.z; o1.w = v1.w + wwn * dv1.w;
            *(float4*)(outp + n * MM + h * 4)      = o0;
            *(float4*)(outp + n * MM + 32 + h * 4) = o1;
        }
        // combine the 4 row-groups (same column sets) across the warp
        #pragma unroll
        for (int o = 16; o >= 8; o >>= 1) {
            racc0.x += __shfl_xor_sync(0xffffffffu, racc0.x, o);
            racc0.y += __shfl_xor_sync(0xffffffffu, racc0.y, o);
            racc0.z += __shfl_xor_sync(0xffffffffu, racc0.z, o);
            racc0.w += __shfl_xor_sync(0xffffffffu, racc0.w, o);
            racc1.x += __shfl_xor_sync(0xffffffffu, racc1.x, o);
            racc1.y += __shfl_xor_sync(0xffffffffu, racc1.y, o);
            racc1.z += __shfl_xor_sync(0xffffffffu, racc1.z, o);
            racc1.w += __shfl_xor_sync(0xffffffffu, racc1.w, o);
        }
        if (lane < 8) {
            *(float4*)&part[wid * 64 + h * 4]      = racc0;
            *(float4*)&part[wid * 64 + 32 + h * 4] = racc1;
        }
    }
    __syncthreads();
    if (tid < 64) {
        float rsum = 0.f;
        #pragma unroll
        for (int w = 0; w < 16; ++w) rsum += part[w * 64 + tid];
        readv[tid] = rsum;
    }
    __syncthreads();

    // ── Epilogue: seq_out[b, o] = sigmoid([ctrl_out, read] @ outW + outb)
    if (tid < 256) {
        const int o = tid >> 5, l = tid & 31;
        float a = 0.f;
        #pragma unroll
        for (int i = l; i < COUT + MM; i += 32) {
            float xi = (i < COUT) ? sCtrl[i] : readv[i - COUT];
            a += xi * sOutW[i * SEQW + o];
        }
        #pragma unroll
        for (int off = 16; off; off >>= 1) a += __shfl_xor_sync(0xffffffffu, a, off);
        if (l == 0) d_out[(size_t)b * SEQW + o] = sigmf(a + sOutB[o]);
    }
}

// ---------------------------------------------------------------------------
extern "C" void kernel_launch(void* const* d_in, const int* in_sizes, int n_in,
                              void* d_out, int out_size)
{
    const float* x         = (const float*)d_in[0];
    const float* prev_read = (const float*)d_in[1];
    const float* bank      = (const float*)d_in[2];
    const float* w_read    = (const float*)d_in[3];
    const float* w_write   = (const float*)d_in[4];
    const float* W0        = (const float*)d_in[5];
    const float* b0        = (const float*)d_in[6];
    const float* W1        = (const float*)d_in[7];
    const float* b1        = (const float*)d_in[8];
    const float* Wout      = (const float*)d_in[9];
    const float* bout      = (const float*)d_in[10];
    const float* reprW     = (const float*)d_in[11];
    const float* reprb     = (const float*)d_in[12];
    const float* outW      = (const float*)d_in[13];
    const float* outb      = (const float*)d_in[14];
    float* out = (float*)d_out;

    ctrl_kernel<<<BB / TB, 256>>>(x, prev_read, W0, b0, W1, b1,
                                  Wout, bout, reprW, reprb);
    ntm_update_kernel<<<BB, 512>>>(bank, w_read, w_write, outW, outb, out);
}